// round 2
// baseline (speedup 1.0000x reference)
#include <cuda_runtime.h>
#include <stdint.h>

#define N_TOK 16384
#define K_CODE 8192
#define DIM 64
#define DECAYF 0.99f
#define OMDF 0.01f
#define EPSF 1e-5f

#define FMA_F32X2(d, a, b, c) \
    asm("fma.rn.f32x2 %0, %1, %2, %3;" : "=l"(d) : "l"(a), "l"(b), "l"(c))

// scratch (device globals: no allocations allowed)
__device__ float g_halfc[K_CODE];          // 0.5*||c||^2
__device__ float g_pval[4 * N_TOK];        // partial min value per code-split
__device__ int   g_pidx[4 * N_TOK];        // partial argmin per code-split
__device__ int   g_idx[N_TOK];             // final argmin
__device__ float g_wacc[K_CODE * DIM];     // scatter-add accumulator
__device__ float g_cnt[K_CODE];            // histogram

// ---------------------------------------------------------------------------
__global__ __launch_bounds__(256) void k_half(const float* __restrict__ cb) {
    int k = blockIdx.x * 256 + threadIdx.x;
    const float4* c4 = (const float4*)(cb + (size_t)k * DIM);
    float s = 0.f;
#pragma unroll
    for (int i = 0; i < 16; i++) {
        float4 v = c4[i];
        s += v.x * v.x + v.y * v.y + v.z * v.z + v.w * v.w;
    }
    g_halfc[k] = 0.5f * s;
}

// ---------------------------------------------------------------------------
// Distance/argmin. grid = (4 code-splits, 256 token-blocks of 64), 128 thr.
// Thread tile: 4 tokens x 4 codes, packed as f32x2 token-pairs (FFMA2).
// Codebook tile stored pre-duplicated in SMEM: for each k, two 128B chunks;
// chunk0[cg] = (b0,b0,b1,b1), chunk1[cg] = (b2,b2,b3,b3) for that cg's 4
// codes -> both LDS.128 are 8 distinct 16B slots per 128B = conflict-free.
__global__ __launch_bounds__(128, 7) void k_dist(const float* __restrict__ x,
                                                 const float* __restrict__ cb,
                                                 float* __restrict__ discrete) {
    __shared__ float As[64 * 64];    // As[k][token], 16KB
    __shared__ float Bs[64 * 64];    // dup layout per k-row (64 floats), 16KB

    const int tid = threadIdx.x;
    const int bx = blockIdx.x;                // code split 0..3
    const int by = blockIdx.y;                // token block 0..255
    const int blin = by * 4 + bx;             // 0..1023
    const int tg = tid >> 3;                  // token group 0..15 (4 tokens)
    const int cg = tid & 7;                   // code group 0..7 (4 codes)

    const float4 z4 = make_float4(0.f, 0.f, 0.f, 0.f);

    // zero scratch accumulators (1024 blocks x 128 threads)
    {
        const int g = blin * 128 + tid;
        ((float4*)g_wacc)[g] = z4;            // 131072 float4
        if (blin < 16) ((float4*)g_cnt)[blin * 128 + tid] = z4;  // 2048 float4
    }

    // load x tile (64 tokens x 64 dims) transposed into As[k][t]
    const float4* x4 = (const float4*)x;
    const int m0 = by * 64;
#pragma unroll
    for (int it = 0; it < 8; it++) {
        int lin = tid + it * 128;
        int t = lin & 63, kq = lin >> 6;
        float4 v = x4[(size_t)(m0 + t) * 16 + kq];
        As[(kq * 4 + 0) * 64 + t] = v.x;
        As[(kq * 4 + 1) * 64 + t] = v.y;
        As[(kq * 4 + 2) * 64 + t] = v.z;
        As[(kq * 4 + 3) * 64 + t] = v.w;
    }
    __syncthreads();

    float minv[4];
    int   mini[4];
#pragma unroll
    for (int i = 0; i < 4; i++) { minv[i] = 3.402823466e38f; mini[i] = 0; }

    // discrete zero-fill slice: 32768 float4 per block, 4/thread/tile
    float4* dz = (float4*)discrete + (size_t)blin * 32768;

    const float4* cb4 = (const float4*)cb;
    const float4* h4 = (const float4*)g_halfc;
    const int cbase = bx * 2048;

    for (int tile = 0; tile < 64; tile++) {
        const int c0 = cbase + tile * 32;
        // fill Bs dup-layout: 32 codes x 16 k-float4 = 512 items, 4/thread
#pragma unroll
        for (int it = 0; it < 4; it++) {
            int lin = tid + it * 128;
            int c = lin & 31, kq = lin >> 5;
            float4 v = cb4[(size_t)(c0 + c) * 16 + kq];
            int off = ((c >> 1) & 1) * 32 + (c >> 2) * 4 + (c & 1) * 2;
            float2* p0 = (float2*)&Bs[(kq * 4 + 0) * 64 + off];
            float2* p1 = (float2*)&Bs[(kq * 4 + 1) * 64 + off];
            float2* p2 = (float2*)&Bs[(kq * 4 + 2) * 64 + off];
            float2* p3 = (float2*)&Bs[(kq * 4 + 3) * 64 + off];
            *p0 = make_float2(v.x, v.x);
            *p1 = make_float2(v.y, v.y);
            *p2 = make_float2(v.z, v.z);
            *p3 = make_float2(v.w, v.w);
        }
        __syncthreads();

        unsigned long long acc[2][4];
#pragma unroll
        for (int i = 0; i < 2; i++)
#pragma unroll
            for (int j = 0; j < 4; j++) acc[i][j] = 0ull;

#pragma unroll 8
        for (int k = 0; k < 64; k++) {
            ulonglong2 a = *(const ulonglong2*)&As[k * 64 + tg * 4];
            ulonglong2 b01 = *(const ulonglong2*)&Bs[k * 64 + cg * 4];
            ulonglong2 b23 = *(const ulonglong2*)&Bs[k * 64 + 32 + cg * 4];
            FMA_F32X2(acc[0][0], a.x, b01.x, acc[0][0]);
            FMA_F32X2(acc[0][1], a.x, b01.y, acc[0][1]);
            FMA_F32X2(acc[0][2], a.x, b23.x, acc[0][2]);
            FMA_F32X2(acc[0][3], a.x, b23.y, acc[0][3]);
            FMA_F32X2(acc[1][0], a.y, b01.x, acc[1][0]);
            FMA_F32X2(acc[1][1], a.y, b01.y, acc[1][1]);
            FMA_F32X2(acc[1][2], a.y, b23.x, acc[1][2]);
            FMA_F32X2(acc[1][3], a.y, b23.y, acc[1][3]);
        }
        __syncthreads();

        // trickle zero-fill of 'discrete'
#pragma unroll
        for (int r = 0; r < 4; r++) dz[(tile * 4 + r) * 128 + tid] = z4;

        // score = 0.5||c||^2 - x.c ; running argmin (strict <, ascending idx)
        float4 h = h4[(c0 >> 2) + cg];
        float hh[4] = {h.x, h.y, h.z, h.w};
        const int cb0 = c0 + cg * 4;
#pragma unroll
        for (int i = 0; i < 2; i++)
#pragma unroll
            for (int j = 0; j < 4; j++) {
                float2 p = *(float2*)&acc[i][j];
                float s0 = hh[j] - p.x;
                float s1 = hh[j] - p.y;
                if (s0 < minv[2 * i]) { minv[2 * i] = s0; mini[2 * i] = cb0 + j; }
                if (s1 < minv[2 * i + 1]) { minv[2 * i + 1] = s1; mini[2 * i + 1] = cb0 + j; }
            }
    }

    // reduce over the 8 code-group lanes, lowest idx on tie
#pragma unroll
    for (int i = 0; i < 4; i++) {
        float v = minv[i];
        int id = mini[i];
#pragma unroll
        for (int off = 4; off; off >>= 1) {
            float ov = __shfl_xor_sync(0xffffffffu, v, off, 8);
            int oi = __shfl_xor_sync(0xffffffffu, id, off, 8);
            if (ov < v || (ov == v && oi < id)) { v = ov; id = oi; }
        }
        if (cg == 0) {
            int tok = m0 + tg * 4 + i;
            g_pval[bx * N_TOK + tok] = v;
            g_pidx[bx * N_TOK + tok] = id;
        }
    }
}

// ---------------------------------------------------------------------------
__global__ __launch_bounds__(256) void k_merge() {
    int n = blockIdx.x * 256 + threadIdx.x;
    float v = g_pval[n];
    int id = g_pidx[n];
#pragma unroll
    for (int s = 1; s < 4; s++) {
        float ov = g_pval[s * N_TOK + n];
        int oi = g_pidx[s * N_TOK + n];
        if (ov < v || (ov == v && oi < id)) { v = ov; id = oi; }
    }
    g_idx[n] = id;
}

// ---------------------------------------------------------------------------
__global__ __launch_bounds__(256) void k_scatter(const float* __restrict__ x,
                                                 const float* __restrict__ cb,
                                                 float* __restrict__ discrete,
                                                 float* __restrict__ quant) {
    int gid = blockIdx.x * 256 + threadIdx.x;  // 0 .. 1048575
    int n = gid >> 6, d = gid & 63;
    int k = g_idx[n];
    quant[gid] = cb[k * DIM + d];
    atomicAdd(&g_wacc[k * DIM + d], x[gid]);
    if (d == 0) {
        atomicAdd(&g_cnt[k], 1.0f);
        discrete[(size_t)n * K_CODE + k] = 1.0f;
    }
}

// ---------------------------------------------------------------------------
__global__ __launch_bounds__(256) void k_count(const float* __restrict__ ema_count,
                                               float* __restrict__ out_count) {
    int k = blockIdx.x * 256 + threadIdx.x;
    float v = ema_count[k] * DECAYF + g_cnt[k] * OMDF;
    out_count[k] = (v + EPSF) / (32.0f + 8192.0f * EPSF) * 32.0f;
}

__global__ __launch_bounds__(256) void k_final(const float* __restrict__ ema_weight,
                                               const float* __restrict__ out_count,
                                               float* __restrict__ out_weight,
                                               float* __restrict__ out_codebook) {
    int gid = blockIdx.x * 256 + threadIdx.x;  // 0 .. 524287
    int k = gid >> 6;
    float nw = ema_weight[gid] * DECAYF + g_wacc[gid] * OMDF;
    out_weight[gid] = nw;
    out_codebook[gid] = nw / out_count[k];
}

// ---------------------------------------------------------------------------
extern "C" void kernel_launch(void* const* d_in, const int* in_sizes, int n_in,
                              void* d_out, int out_size) {
    const float* x = (const float*)d_in[0];           // 16384 x 64
    const float* cb = (const float*)d_in[1];          // 8192 x 64
    const float* ema_count = (const float*)d_in[2];   // 8192
    const float* ema_weight = (const float*)d_in[3];  // 8192 x 64

    float* out = (float*)d_out;
    float* o_disc = out;                                   // 134217728
    float* o_quant = o_disc + (size_t)N_TOK * K_CODE;      // 1048576
    float* o_cnt = o_quant + (size_t)N_TOK * DIM;          // 8192
    float* o_w = o_cnt + K_CODE;                           // 524288
    float* o_cb = o_w + (size_t)K_CODE * DIM;              // 524288

    k_half<<<K_CODE / 256, 256>>>(cb);
    k_dist<<<dim3(4, 256, 1), 128>>>(x, cb, o_disc);
    k_merge<<<N_TOK / 256, 256>>>();
    k_scatter<<<(N_TOK * DIM) / 256, 256>>>(x, cb, o_disc, o_quant);
    k_count<<<K_CODE / 256, 256>>>(ema_count, o_cnt);
    k_final<<<(K_CODE * DIM) / 256, 256>>>(ema_weight, o_cnt, o_w, o_cb);
}